// round 8
// baseline (speedup 1.0000x reference)
#include <cuda_runtime.h>
#include <cstdint>

// ---------------- problem constants ----------------
#define NPOS   8192          // 64 x 128 spatial positions (x1|x2 concat)
#define NCH    64
#define KC     8
#define TQ     64            // kv chunk length staged in smem (double-buffered)
#define ATT_SCALE 0.35355339059327373f   // 8^-0.5

// ---------------- scratch (device globals; no allocations) ----------------
__device__ float g_Q[4 * KC * NPOS];        // [stage][k][blocked-pos]
__device__ float g_K[4 * KC * NPOS];
__device__ float g_V[4 * NCH * NPOS];       // [stage][c][blocked-pos]
__device__ float g_ctx[4 * NCH * NPOS];     // context, blocked layout
__device__ float g_pacc0[32 * NCH * NPOS];  // stage-0 split partial acc
__device__ float g_pacc1[8 * NCH * NPOS];   // stage-1 split partial acc
__device__ float g_pl0[32 * NPOS];          // stage-0 split partial l
__device__ float g_pl1[8 * NPOS];           // stage-1 split partial l

// ---------------- packed f32x2 helpers ----------------
typedef unsigned long long u64;

__device__ __forceinline__ u64 pack2(float lo, float hi) {
    u64 r;
    asm("mov.b64 %0, {%1, %2};" : "=l"(r) : "f"(lo), "f"(hi));
    return r;
}
__device__ __forceinline__ void unpack2(u64 v, float& lo, float& hi) {
    asm("mov.b64 {%0, %1}, %2;" : "=f"(lo), "=f"(hi) : "l"(v));
}
__device__ __forceinline__ u64 fma2(u64 a, u64 b, u64 c) {
    u64 d;
    asm("fma.rn.f32x2 %0, %1, %2, %3;" : "=l"(d) : "l"(a), "l"(b), "l"(c));
    return d;
}
__device__ __forceinline__ u64 mul2(u64 a, u64 b) {
    u64 d;
    asm("mul.rn.f32x2 %0, %1, %2;" : "=l"(d) : "l"(a), "l"(b));
    return d;
}

// ---------------- cp.async helpers ----------------
__device__ __forceinline__ void cpasync4(uint32_t dst, const float* src) {
    asm volatile("cp.async.ca.shared.global [%0], [%1], 4;" :: "r"(dst), "l"(src));
}
#define CP_COMMIT() asm volatile("cp.async.commit_group;" ::: "memory")
#define CP_WAIT0()  asm volatile("cp.async.wait_group 0;"  ::: "memory")

// Blocked index: stage s (scale = 2^s), flat pos (h*128 + wfull) ->
// block * Pb + p, matching the reference's to_blocks() permutation.
__device__ __forceinline__ int blocked_idx(int s, int pos) {
    int h    = pos >> 7;
    int wf   = pos & 127;
    int half = wf >> 6;
    int w    = wf & 63;
    int l2hl = 6 - s;                 // log2(block edge)
    int msk  = (1 << l2hl) - 1;
    int bi = h >> l2hl, r = h & msk;
    int bj = w >> l2hl, c = w & msk;
    int block = (bi << s) + bj;
    int p  = (((r << l2hl) + c) << 1) + half;
    int Pb = 1 << (2 * l2hl + 1);     // hl*wl*2
    return block * Pb + p;
}

// ================= kernel 1: QKV projections (BN folded), blocked layout ===
__global__ void __launch_bounds__(256) qkv_kernel(
    const float* __restrict__ x1, const float* __restrict__ x2,
    const float* __restrict__ Wq, const float* __restrict__ bq,
    const float* __restrict__ gq, const float* __restrict__ betq,
    const float* __restrict__ Wk, const float* __restrict__ bk,
    const float* __restrict__ gk, const float* __restrict__ betk,
    const float* __restrict__ Wv, const float* __restrict__ bv)
{
    __shared__ float w_s[80 * 64];   // 8 q + 8 k + 64 v effective rows
    __shared__ float b_s[80];
    __shared__ float xs[64 * 64];    // [c][p]

    const int s   = blockIdx.y;      // stage (scale = 2^s)
    const int til = blockIdx.x;      // 0..127 position tiles of 64
    const int tid = threadIdx.x;

    for (int i = tid; i < 80 * 64; i += 256) {
        int r = i >> 6, c = i & 63;
        float w;
        if (r < 8)       w = gq[s * 8 + r] * Wq[(s * 8 + r) * 64 + c];
        else if (r < 16) w = gk[s * 8 + (r - 8)] * Wk[(s * 8 + (r - 8)) * 64 + c];
        else             w = Wv[(s * 64 + (r - 16)) * 64 + c];
        w_s[i] = w;
    }
    if (tid < 80) {
        int r = tid;
        float b;
        if (r < 8)       b = gq[s * 8 + r] * bq[s * 8 + r] + betq[s * 8 + r];
        else if (r < 16) b = gk[s * 8 + (r - 8)] * bk[s * 8 + (r - 8)] + betk[s * 8 + (r - 8)];
        else             b = bv[s * 64 + (r - 16)];
        b_s[r] = b;
    }
    const int pos0 = til * 64;
    for (int i = tid; i < 64 * 64; i += 256) {
        int c = i >> 6, p = i & 63;
        int pos = pos0 + p;
        int h = pos >> 7, wf = pos & 127;
        xs[c * 64 + p] = (wf < 64) ? x1[c * 4096 + h * 64 + wf]
                                   : x2[c * 4096 + h * 64 + (wf - 64)];
    }
    __syncthreads();

    const int p = tid & 63;
    const int g = tid >> 6;          // 4 thread groups, 20 rows each
    float acc[20];
    #pragma unroll
    for (int j = 0; j < 20; j++) acc[j] = b_s[g + 4 * j];

    for (int c = 0; c < 64; c++) {
        float xv = xs[c * 64 + p];
        #pragma unroll
        for (int j = 0; j < 20; j++)
            acc[j] += w_s[(g + 4 * j) * 64 + c] * xv;
    }

    const int bidx = blocked_idx(s, pos0 + p);
    #pragma unroll
    for (int j = 0; j < 20; j++) {
        int r = g + 4 * j;
        if (r < 8)       g_Q[(s * KC + r) * NPOS + bidx] = acc[j];
        else if (r < 16) g_K[(s * KC + (r - 8)) * NPOS + bidx] = acc[j];
        else             g_V[(s * NCH + (r - 16)) * NPOS + bidx] = acc[j];
    }
}

// ================= kernel 2: block attention ===============================
// 128 threads/CTA, 2 queries/thread. CTA durations chosen for wave balance:
// long stage-2 CTAs first (bids 0..31), ~uniform 256-kv CTAs in the middle,
// short stage-3 CTAs last. Softmax with fixed shift 0 (exact by invariance).
// KV chunks streamed with cp.async double buffering.

// Issue one chunk's K/V loads into smem buffer via cp.async (no commit).
// Layout per buffer: 18 quad-rows (2 K + 16 V) x TQ columns x 4 floats.
__device__ __forceinline__ void load_chunk(uint32_t buf_base,
                                           const float* __restrict__ Kb,
                                           const float* __restrict__ Vb,
                                           int c0, int tid)
{
    #pragma unroll
    for (int it = 0; it < 9; it++) {          // 18*TQ / 128 threads
        int i   = tid + it * 128;
        int row = i >> 6;                     // TQ = 64
        int q   = i & (TQ - 1);
        const float* src = (row < 2)
            ? (Kb + (4 * row) * NPOS + c0 + q)
            : (Vb + (4 * (row - 2)) * NPOS + c0 + q);
        uint32_t d = buf_base + i * 16;
        cpasync4(d,      src);
        cpasync4(d + 4,  src + NPOS);
        cpasync4(d + 8,  src + 2 * NPOS);
        cpasync4(d + 12, src + 3 * NPOS);
    }
}

__global__ void __launch_bounds__(128, 2) attn_kernel()
{
    __shared__ __align__(16) float KVf[2][18 * TQ * 4];   // 2 x 18KB

    const int bid = blockIdx.x;
    const int tid = threadIdx.x;

    int stage, bb, q0, split, kv0, nchunks, nq;
    if (bid < 32) {                           // stage 2 (long CTAs first): 16 blk x 2 qt
        stage = 2;
        bb = (bid >> 1) * 512; q0 = (bid & 1) * 256;
        split = 0; kv0 = 0; nchunks = 8; nq = 256;
    } else if (bid < 1056) {                  // stage 0: 32 qt x 32 kv-splits
        int i = bid - 32; stage = 0; bb = 0;
        q0 = (i >> 5) * 256;
        split = i & 31; kv0 = split * 256; nchunks = 4; nq = 256;
    } else if (bid < 1312) {                  // stage 1: 32 qt x 8 kv-splits
        int i = bid - 1056; stage = 1;
        int qt = i >> 3; split = i & 7;
        bb = (qt >> 3) * 2048; q0 = (qt & 7) * 256;
        kv0 = split * 256; nchunks = 4; nq = 256;
    } else {                                  // stage 3 (short CTAs last): 64 blocks
        int i = bid - 1312; stage = 3;
        bb = i * 128; q0 = 0;
        split = 0; kv0 = 0; nchunks = 2; nq = 128;
    }

    const int half   = nq >> 1;
    const bool active = tid < half;
    const bool wactive = (tid & ~31) < half;   // warp-uniform compute guard
    const int ta = active ? tid : 0;
    const int qa = q0 + ta;
    const int qb = qa + (active ? half : 0);

    const float* Qp = g_Q + stage * KC * NPOS + bb;
    const float* Kb = g_K + stage * KC * NPOS + bb;
    const float* Vb = g_V + stage * NCH * NPOS + bb;

    const uint32_t smem0 = (uint32_t)__cvta_generic_to_shared(&KVf[0][0]);
    const uint32_t smem1 = (uint32_t)__cvta_generic_to_shared(&KVf[1][0]);

    u64 qa2[4], qb2[4];
    #pragma unroll
    for (int j = 0; j < 4; j++) {
        qa2[j] = pack2(Qp[(2 * j) * NPOS + qa] * ATT_SCALE,
                       Qp[(2 * j + 1) * NPOS + qa] * ATT_SCALE);
        qb2[j] = pack2(Qp[(2 * j) * NPOS + qb] * ATT_SCALE,
                       Qp[(2 * j + 1) * NPOS + qb] * ATT_SCALE);
    }

    u64 acca[32], accb[32];
    #pragma unroll
    for (int j = 0; j < 32; j++) { acca[j] = 0ull; accb[j] = 0ull; }
    float la = 0.0f, lb = 0.0f;

    // prologue: start chunk 0
    load_chunk(smem0, Kb, Vb, kv0, tid);
    CP_COMMIT();

    for (int ch = 0; ch < nchunks; ch++) {
        CP_WAIT0();
        __syncthreads();                       // buf[cur] ready; buf[cur^1] free
        const int cur = ch & 1;
        if (ch + 1 < nchunks) {
            load_chunk(cur ? smem0 : smem1, Kb, Vb, kv0 + (ch + 1) * TQ, tid);
            CP_COMMIT();
        }
        const ulonglong2* KB = (const ulonglong2*)&KVf[cur][0];

        if (wactive) {
            #pragma unroll 2
            for (int q = 0; q < TQ; q++) {
                ulonglong2 k01 = KB[q];
                ulonglong2 k23 = KB[TQ + q];
                u64 da = mul2(qa2[0], k01.x);
                da = fma2(qa2[1], k01.y, da);
                da = fma2(qa2[2], k23.x, da);
                da = fma2(qa2[3], k23.y, da);
                u64 db = mul2(qb2[0], k01.x);
                db = fma2(qb2[1], k01.y, db);
                db = fma2(qb2[2], k23.x, db);
                db = fma2(qb2[3], k23.y, db);
                float a0, a1, b0, b1;
                unpack2(da, a0, a1);
                unpack2(db, b0, b1);
                float ea = __expf(a0 + a1);  la += ea;
                float eb = __expf(b0 + b1);  lb += eb;
                u64 ea2 = pack2(ea, ea);
                u64 eb2 = pack2(eb, eb);
                #pragma unroll
                for (int jj = 0; jj < 16; jj++) {
                    ulonglong2 v = KB[(2 + jj) * TQ + q];
                    acca[2 * jj]     = fma2(ea2, v.x, acca[2 * jj]);
                    acca[2 * jj + 1] = fma2(ea2, v.y, acca[2 * jj + 1]);
                    accb[2 * jj]     = fma2(eb2, v.x, accb[2 * jj]);
                    accb[2 * jj + 1] = fma2(eb2, v.y, accb[2 * jj + 1]);
                }
            }
        }
    }

    if (!active) return;

    if (stage <= 1) {                         // raw split partials
        float* pl = (stage == 0) ? g_pl0 : g_pl1;
        float* pa = (stage == 0) ? g_pacc0 : g_pacc1;
        pl[split * NPOS + bb + qa] = la;
        pl[split * NPOS + bb + qb] = lb;
        float* da_ = pa + split * NCH * NPOS + bb + qa;
        float* db_ = pa + split * NCH * NPOS + bb + qb;
        #pragma unroll
        for (int j = 0; j < 32; j++) {
            float lo, hi;
            unpack2(acca[j], lo, hi);
            da_[(2 * j) * NPOS] = lo;  da_[(2 * j + 1) * NPOS] = hi;
            unpack2(accb[j], lo, hi);
            db_[(2 * j) * NPOS] = lo;  db_[(2 * j + 1) * NPOS] = hi;
        }
    } else {                                  // finalize directly
        float ia = 1.0f / la, ib = 1.0f / lb;
        float* da_ = g_ctx + stage * NCH * NPOS + bb + qa;
        float* db_ = g_ctx + stage * NCH * NPOS + bb + qb;
        #pragma unroll
        for (int j = 0; j < 32; j++) {
            float lo, hi;
            unpack2(acca[j], lo, hi);
            da_[(2 * j) * NPOS] = lo * ia;  da_[(2 * j + 1) * NPOS] = hi * ia;
            unpack2(accb[j], lo, hi);
            db_[(2 * j) * NPOS] = lo * ib;  db_[(2 * j + 1) * NPOS] = hi * ib;
        }
    }
}

// ================= kernel 3: split merge (stages 0 and 1) ==================
// 128 CTAs x 256 threads: each thread merges 8 channels of one q4-group.
__global__ void __launch_bounds__(256) merge_kernel()
{
    int t = blockIdx.x * 256 + threadIdx.x;   // 0..32767
    int r  = t & 16383;
    int q4 = (r >> 3) * 4;                    // 2048 q-groups per stage
    int cg = (r & 7) * 8;                     // 8-channel group base
    if (t < 16384) {                          // stage 0: 32 splits
        float4 d = make_float4(0.f, 0.f, 0.f, 0.f);
        #pragma unroll
        for (int i = 0; i < 32; i++) {
            float4 l = *(const float4*)(g_pl0 + i * NPOS + q4);
            d.x += l.x; d.y += l.y; d.z += l.z; d.w += l.w;
        }
        float4 inv = make_float4(1.f / d.x, 1.f / d.y, 1.f / d.z, 1.f / d.w);
        #pragma unroll 2
        for (int cc = 0; cc < 8; cc++) {
            int c = cg + cc;
            float4 v = make_float4(0.f, 0.f, 0.f, 0.f);
            #pragma unroll
            for (int i = 0; i < 32; i++) {
                float4 a = *(const float4*)(g_pacc0 + (i * NCH + c) * NPOS + q4);
                v.x += a.x; v.y += a.y; v.z += a.z; v.w += a.w;
            }
            v.x *= inv.x; v.y *= inv.y; v.z *= inv.z; v.w *= inv.w;
            *(float4*)(g_ctx + c * NPOS + q4) = v;
        }
    } else {                                  // stage 1: 8 splits
        float4 d = make_float4(0.f, 0.f, 0.f, 0.f);
        #pragma unroll
        for (int i = 0; i < 8; i++) {
            float4 l = *(const float4*)(g_pl1 + i * NPOS + q4);
            d.x += l.x; d.y += l.y; d.z += l.z; d.w += l.w;
        }
        float4 inv = make_float4(1.f / d.x, 1.f / d.y, 1.f / d.z, 1.f / d.w);
        #pragma unroll 2
        for (int cc = 0; cc < 8; cc++) {
            int c = cg + cc;
            float4 v = make_float4(0.f, 0.f, 0.f, 0.f);
            #pragma unroll
            for (int i = 0; i < 8; i++) {
                float4 a = *(const float4*)(g_pacc1 + (i * NCH + c) * NPOS + q4);
                v.x += a.x; v.y += a.y; v.z += a.z; v.w += a.w;
            }
            v.x *= inv.x; v.y *= inv.y; v.z *= inv.z; v.w *= inv.w;
            *(float4*)(g_ctx + NCH * NPOS + c * NPOS + q4) = v;
        }
    }
}

// ================= kernel 4: final 1x1 conv (Wo @ cat(ctx)) ================
__global__ void __launch_bounds__(128) final_kernel(
    const float* __restrict__ Wo, float* __restrict__ out)
{
    __shared__ __align__(16) float wo_s[256 * 32];    // [d][o'] for this o-half
    const int tid = threadIdx.x;
    const int oh  = blockIdx.y;                       // output-channel half

    for (int i = tid; i < 256 * 32; i += 128) {
        int d = i >> 5, o = i & 31;
        wo_s[i] = Wo[(oh * 32 + o) * 256 + d];
    }
    __syncthreads();

    const int pos = blockIdx.x * 128 + tid;
    u64 acc2[16];
    #pragma unroll
    for (int j = 0; j < 16; j++) acc2[j] = 0ull;

    #pragma unroll
    for (int s = 0; s < 4; s++) {
        int bx = blocked_idx(s, pos);
        const float* cp = g_ctx + s * NCH * NPOS + bx;
        #pragma unroll 8
        for (int dd = 0; dd < 64; dd++) {
            float cv = cp[dd * NPOS];
            u64 cv2 = pack2(cv, cv);
            const u64* wrow = (const u64*)(wo_s + (s * 64 + dd) * 32);
            #pragma unroll
            for (int j = 0; j < 16; j++)
                acc2[j] = fma2(cv2, wrow[j], acc2[j]);
        }
    }

    const int h = pos >> 7, wf = pos & 127;
    float* ob = out + ((wf < 64) ? (h * 64 + wf) : (262144 + h * 64 + (wf - 64)));
    #pragma unroll
    for (int j = 0; j < 16; j++) {
        float lo, hi;
        unpack2(acc2[j], lo, hi);
        ob[(oh * 32 + 2 * j) * 4096]     = lo;
        ob[(oh * 32 + 2 * j + 1) * 4096] = hi;
    }
}

// ================= launch ==================================================
extern "C" void kernel_launch(void* const* d_in, const int* in_sizes, int n_in,
                              void* d_out, int out_size)
{
    const float* x1   = (const float*)d_in[0];
    const float* x2   = (const float*)d_in[1];
    const float* Wq   = (const float*)d_in[2];
    const float* bq   = (const float*)d_in[3];
    const float* gq   = (const float*)d_in[4];
    const float* betq = (const float*)d_in[5];
    const float* Wk   = (const float*)d_in[6];
    const float* bk   = (const float*)d_in[7];
    const float* gk   = (const float*)d_in[8];
    const float* betk = (const float*)d_in[9];
    const float* Wv   = (const float*)d_in[10];
    const float* bv   = (const float*)d_in[11];
    const float* Wo   = (const float*)d_in[12];
    float* out = (float*)d_out;

    qkv_kernel<<<dim3(128, 4), 256>>>(x1, x2, Wq, bq, gq, betq,
                                      Wk, bk, gk, betk, Wv, bv);
    attn_kernel<<<1376, 128>>>();
    merge_kernel<<<128, 256>>>();
    final_kernel<<<dim3(64, 2), 128>>>(Wo, out);
}